// round 5
// baseline (speedup 1.0000x reference)
#include <cuda_runtime.h>

#define NNODES 100000
#define NEDGES 1600000
#define F0 128
#define F1 64
#define F2 16
#define NB1 ((NNODES + 255) / 256)   // 391 scan blocks

typedef unsigned long long ull;

// Scratch (device globals: allocation-free, graph-safe)
__device__ float g_dinv[NNODES];
__device__ float g_h1  [NNODES * F1];   // h~ = (x@W1)*dinv[row]
__device__ float g_t   [NNODES * F1];   // activated layer-1 output
__device__ float g_h2  [NNODES * F2];   // h~2 = (t@W2)*dinv[row]
// dst-CSR scratch
__device__ int   g_hist  [NNODES];      // in-degree (dst)
__device__ int   g_off   [NNODES];
__device__ int   g_rowptr[NNODES];
__device__ int   g_cursor[NNODES];
__device__ int   g_bsum  [512];
__device__ int   g_csr   [NEDGES];      // src ids grouped by dst

// ---------------------------------------------------------------------------
// f32x2 packed helpers (sm_103a FFMA2 — only reachable via PTX)
// ---------------------------------------------------------------------------
__device__ __forceinline__ ull pack2(float lo, float hi) {
    ull r; asm("mov.b64 %0, {%1, %2};" : "=l"(r) : "f"(lo), "f"(hi)); return r;
}
__device__ __forceinline__ void unpack2(ull v, float& lo, float& hi) {
    asm("mov.b64 {%0, %1}, %2;" : "=f"(lo), "=f"(hi) : "l"(v));
}
__device__ __forceinline__ void fma2(ull& acc, ull a, ull b) {
    asm("fma.rn.f32x2 %0, %1, %2, %0;" : "+l"(acc) : "l"(a), "l"(b));
}
__device__ __forceinline__ ull mul2(ull a, ull b) {
    ull r; asm("mul.rn.f32x2 %0, %1, %2;" : "=l"(r) : "l"(a), "l"(b)); return r;
}

// ---------------------------------------------------------------------------
// 1. Init: zero dst histogram
// ---------------------------------------------------------------------------
__global__ void gcn_init_kernel() {
    int i = blockIdx.x * blockDim.x + threadIdx.x;
    if (i < NNODES) g_hist[i] = 0;
}

// ---------------------------------------------------------------------------
// 2. In-degree histogram over dst (deg = 1 + hist)
// ---------------------------------------------------------------------------
__global__ void gcn_hist_kernel(const int* __restrict__ dst) {
    int e = blockIdx.x * blockDim.x + threadIdx.x;
    if (e < NEDGES) atomicAdd(&g_hist[dst[e]], 1);
}

// ---------------------------------------------------------------------------
// 3. dinv = rsqrt(1 + indeg)
// ---------------------------------------------------------------------------
__global__ void gcn_dinv_kernel() {
    int i = blockIdx.x * blockDim.x + threadIdx.x;
    if (i < NNODES) g_dinv[i] = rsqrtf(1.0f + (float)g_hist[i]);
}

// ---------------------------------------------------------------------------
// 4. GEMM1: h1[v,:] = (x[v,:] @ W1) * dinv[v]     [N,128]x[128,64]
// Row-pair FFMA2:
//   xs[k][rp] = (x[2rp][k], x[2rp+1][k])  -- k-major row-pairs, staged in
//               2 chunks of 64 k, conflict-free transposed stores
//   wd[k][c]  = (W[k][c], W[k][c])        -- duplicated W (one-time 68KB)
// Thread tile 8 rows x 4 cols = 16 FMA2/k from 4 LDS.128 (4B/FMA2, no movs).
// 256 threads, BM=128 rows, 2 blocks/SM (99KB smem).
// ---------------------------------------------------------------------------
#define BM 128
#define KC 64                 // k-chunk
#define P2 66                 // float2 pitch per k-slice (16B-aligned, padded)
extern __shared__ float2 s_g1[];   // wd[F0*P2] then xs[KC*P2]

__global__ void __launch_bounds__(256, 2) gcn_gemm1_kernel(
        const float* __restrict__ x, const float* __restrict__ W1) {
    float2* wd = s_g1;                 // F0 * P2 float2 = 67.6 KB
    float2* xs = s_g1 + F0 * P2;       // KC * P2 float2 = 33.8 KB
    int tid = threadIdx.x;
    int row0 = blockIdx.x * BM;

    // Stage duplicated W (one time): wd[k*P2 + c] = (W[k][c], W[k][c])
    for (int i = tid; i < F0 * F1; i += 256) {
        int k = i >> 6, c = i & 63;
        float w = W1[i];
        wd[k * P2 + c] = make_float2(w, w);
    }

    int ty = tid >> 4;          // 0..15 -> rows 8*ty..8*ty+7 (rp 4ty..4ty+3)
    int tx = tid & 15;          // 0..15 -> cols 4*tx..4*tx+3

    ull acc[4][4];              // [rp][c] = (sum_row0, sum_row1)
#pragma unroll
    for (int p = 0; p < 4; p++)
#pragma unroll
        for (int c = 0; c < 4; c++) acc[p][c] = 0ull;

    const float2* xp = xs + 4 * ty;
    const float2* wp0 = wd + 4 * tx;

    for (int kc = 0; kc < F0; kc += KC) {
        __syncthreads();   // previous chunk's reads done before overwrite
        // Stage xs for k in [kc, kc+KC): 1024 tasks, 4 iters/thread.
        // task: rp (64) x k4 (16 quads). Lane mapping keeps stores
        // conflict-free: half-warp covers rp 0..15 at one k-quad.
        for (int i = tid; i < 1024; i += 256) {
            int rp16 = i & 15;
            int k4   = (i >> 4) & 15;      // quad within chunk
            int rb   = i >> 8;             // 0..3
            int rp   = rp16 + 16 * rb;
            int v0   = row0 + 2 * rp;
            int kbase = kc + 4 * k4;
            float4 a = (v0 < NNODES) ? *(const float4*)&x[v0 * F0 + kbase]
                                     : make_float4(0.f, 0.f, 0.f, 0.f);
            float4 b = (v0 + 1 < NNODES) ? *(const float4*)&x[(v0 + 1) * F0 + kbase]
                                         : make_float4(0.f, 0.f, 0.f, 0.f);
            float2* dstp = &xs[(4 * k4) * P2 + rp];
            dstp[0 * P2] = make_float2(a.x, b.x);
            dstp[1 * P2] = make_float2(a.y, b.y);
            dstp[2 * P2] = make_float2(a.z, b.z);
            dstp[3 * P2] = make_float2(a.w, b.w);
        }
        __syncthreads();

#pragma unroll 4
        for (int kk = 0; kk < KC; kk++) {
            int k = kc + kk;
            ulonglong2 px01 = *(const ulonglong2*)(xp + kk * P2);
            ulonglong2 px23 = *(const ulonglong2*)(xp + kk * P2 + 2);
            ulonglong2 w01  = *(const ulonglong2*)(wp0 + k * P2);
            ulonglong2 w23  = *(const ulonglong2*)(wp0 + k * P2 + 2);
            ull px[4] = { px01.x, px01.y, px23.x, px23.y };
            ull wv[4] = { w01.x,  w01.y,  w23.x,  w23.y  };
#pragma unroll
            for (int p = 0; p < 4; p++) {
                fma2(acc[p][0], px[p], wv[0]);
                fma2(acc[p][1], px[p], wv[1]);
                fma2(acc[p][2], px[p], wv[2]);
                fma2(acc[p][3], px[p], wv[3]);
            }
        }
    }

    // Epilogue: scale by dinv, store one float4 per row
#pragma unroll
    for (int p = 0; p < 4; p++) {
        int v0 = row0 + ty * 8 + 2 * p;
        if (v0 >= NNODES) continue;
        float d0 = g_dinv[v0];
        float d1 = (v0 + 1 < NNODES) ? g_dinv[v0 + 1] : 0.f;
        ull dd = pack2(d0, d1);
        float lo[4], hi[4];
#pragma unroll
        for (int c = 0; c < 4; c++)
            unpack2(mul2(acc[p][c], dd), lo[c], hi[c]);
        *(float4*)&g_h1[v0 * F1 + tx * 4] = make_float4(lo[0], lo[1], lo[2], lo[3]);
        if (v0 + 1 < NNODES)
            *(float4*)&g_h1[(v0 + 1) * F1 + tx * 4] = make_float4(hi[0], hi[1], hi[2], hi[3]);
    }
}

// ---------------------------------------------------------------------------
// 5-7. Two-level exclusive scan of g_hist -> rowptr + cursor
// ---------------------------------------------------------------------------
__global__ void gcn_scan1_kernel() {
    __shared__ int s[256];
    int tid = threadIdx.x;
    int i = blockIdx.x * 256 + tid;
    int v = (i < NNODES) ? g_hist[i] : 0;
    s[tid] = v;
    __syncthreads();
#pragma unroll
    for (int o = 1; o < 256; o <<= 1) {
        int t = (tid >= o) ? s[tid - o] : 0;
        __syncthreads();
        s[tid] += t;
        __syncthreads();
    }
    if (i < NNODES) g_off[i] = s[tid] - v;
    if (tid == 255) g_bsum[blockIdx.x] = s[255];
}

__global__ void gcn_scan2_kernel() {
    __shared__ int s[512];
    int tid = threadIdx.x;
    int v = (tid < NB1) ? g_bsum[tid] : 0;
    s[tid] = v;
    __syncthreads();
#pragma unroll
    for (int o = 1; o < 512; o <<= 1) {
        int t = (tid >= o) ? s[tid - o] : 0;
        __syncthreads();
        s[tid] += t;
        __syncthreads();
    }
    if (tid < NB1) g_bsum[tid] = s[tid] - v;
}

__global__ void gcn_rowptr_kernel() {
    int i = blockIdx.x * blockDim.x + threadIdx.x;
    if (i < NNODES) {
        int p = g_off[i] + g_bsum[i >> 8];
        g_rowptr[i] = p;
        g_cursor[i] = p;
    }
}

// ---------------------------------------------------------------------------
// 8. Permute: group src ids by dst (CSR fill)
// ---------------------------------------------------------------------------
__global__ void gcn_permute_kernel(const int* __restrict__ src,
                                   const int* __restrict__ dst) {
    int e = blockIdx.x * blockDim.x + threadIdx.x;
    if (e < NEDGES) {
        int d = dst[e];
        int p = atomicAdd(&g_cursor[d], 1);
        g_csr[p] = src[e];
    }
}

// ---------------------------------------------------------------------------
// 9. Layer-1 aggregation + activation (warp per node, float2 per lane):
//    t[v] = leaky_relu(dinv[v] * (h1[v] + sum_{s->v} h1[s]) + b1)
// ---------------------------------------------------------------------------
__global__ void gcn_agg1_kernel(const float* __restrict__ b1) {
    int w = (blockIdx.x * blockDim.x + threadIdx.x) >> 5;
    int lane = threadIdx.x & 31;
    if (w >= NNODES) return;
    int v = w;
    int beg = g_rowptr[v];
    int len = g_hist[v];

    float2 acc = *(const float2*)&g_h1[v * F1 + lane * 2];   // self loop

    const int* __restrict__ idx = &g_csr[beg];
    int i = 0;
    for (; i + 4 <= len; i += 4) {
        int s0 = idx[i], s1 = idx[i + 1], s2 = idx[i + 2], s3 = idx[i + 3];
        float2 u0 = *(const float2*)&g_h1[s0 * F1 + lane * 2];
        float2 u1 = *(const float2*)&g_h1[s1 * F1 + lane * 2];
        float2 u2 = *(const float2*)&g_h1[s2 * F1 + lane * 2];
        float2 u3 = *(const float2*)&g_h1[s3 * F1 + lane * 2];
        acc.x += u0.x + u1.x + u2.x + u3.x;
        acc.y += u0.y + u1.y + u2.y + u3.y;
    }
    for (; i < len; i++) {
        int s = idx[i];
        float2 u = *(const float2*)&g_h1[s * F1 + lane * 2];
        acc.x += u.x; acc.y += u.y;
    }

    float dv = g_dinv[v];
    float t0 = dv * acc.x + b1[lane * 2];
    float t1 = dv * acc.y + b1[lane * 2 + 1];
    t0 = t0 >= 0.f ? t0 : 0.2f * t0;
    t1 = t1 >= 0.f ? t1 : 0.2f * t1;
    *(float2*)&g_t[v * F1 + lane * 2] = make_float2(t0, t1);
}

// ---------------------------------------------------------------------------
// 10. GEMM2: h2[v,:] = (t[v,:] @ W2) * dinv[v]    [N,64]x[64,16]
// ---------------------------------------------------------------------------
__global__ void gcn_gemm2_kernel(const float* __restrict__ W2) {
    __shared__ __align__(16) float W2s[F1 * F2];
    __shared__ __align__(16) float ts[16][F1];
    int tid = threadIdx.x;
    for (int i = tid; i < F1 * F2; i += 256) W2s[i] = W2[i];

    int v0 = blockIdx.x * 16;
    for (int i = tid; i < 16 * 16; i += 256) {
        int r = i >> 4, q = i & 15;
        *(float4*)&ts[r][q * 4] = *(const float4*)&g_t[(v0 + r) * F1 + q * 4];
    }
    __syncthreads();

    int r = tid >> 4;
    int m = tid & 15;
    int v = v0 + r;
    float acc = 0.f;
#pragma unroll
    for (int j = 0; j < F1; j++) acc += ts[r][j] * W2s[j * F2 + m];
    g_h2[v * F2 + m] = acc * g_dinv[v];
}

// ---------------------------------------------------------------------------
// 11. Layer-2 aggregation + log_softmax (warp per node)
// ---------------------------------------------------------------------------
__global__ void gcn_agg2_kernel(const float* __restrict__ b2,
                                float* __restrict__ out) {
    int w = (blockIdx.x * blockDim.x + threadIdx.x) >> 5;
    int lane = threadIdx.x & 31;
    if (w >= NNODES) return;
    int v = w;
    int beg = g_rowptr[v];
    int len = g_hist[v];
    int f = lane & 15;

    float acc = 0.f;
    const int* __restrict__ idx = &g_csr[beg];
    for (int i = (lane >> 4); i < len; i += 2) {
        int s = idx[i];
        acc += g_h2[s * F2 + f];
    }
    acc += __shfl_down_sync(0xffffffffu, acc, 16);

    float dv = g_dinv[v];
    float t = dv * (acc + g_h2[v * F2 + f]) + b2[f];

    float mx = t;
#pragma unroll
    for (int o = 8; o >= 1; o >>= 1)
        mx = fmaxf(mx, __shfl_xor_sync(0xffffffffu, mx, o));
    float ex = expf(t - mx);
    float sum = ex;
#pragma unroll
    for (int o = 8; o >= 1; o >>= 1)
        sum += __shfl_xor_sync(0xffffffffu, sum, o);
    float lse = mx + logf(sum);

    if (lane < 16) out[v * F2 + f] = t - lse;
}

// ---------------------------------------------------------------------------
// Launch
// ---------------------------------------------------------------------------
extern "C" void kernel_launch(void* const* d_in, const int* in_sizes, int n_in,
                              void* d_out, int out_size) {
    const float* x  = (const float*)d_in[0];
    const int*   ei = (const int*)  d_in[1];
    const float* W1 = (const float*)d_in[2];
    const float* b1 = (const float*)d_in[3];
    const float* W2 = (const float*)d_in[4];
    const float* b2 = (const float*)d_in[5];
    float* out = (float*)d_out;

    const int* src = ei;
    const int* dst = ei + NEDGES;

    const int gemm1_smem = (F0 * P2 + KC * P2) * (int)sizeof(float2); // ~99 KB
    cudaFuncSetAttribute(gcn_gemm1_kernel,
                         cudaFuncAttributeMaxDynamicSharedMemorySize, gemm1_smem);

    gcn_init_kernel   <<<(NNODES + 255) / 256, 256>>>();
    gcn_hist_kernel   <<<(NEDGES + 255) / 256, 256>>>(dst);
    gcn_dinv_kernel   <<<(NNODES + 255) / 256, 256>>>();
    gcn_gemm1_kernel  <<<(NNODES + BM - 1) / BM, 256, gemm1_smem>>>(x, W1);
    gcn_scan1_kernel  <<<NB1, 256>>>();
    gcn_scan2_kernel  <<<1, 512>>>();
    gcn_rowptr_kernel <<<(NNODES + 255) / 256, 256>>>();
    gcn_permute_kernel<<<(NEDGES + 255) / 256, 256>>>(src, dst);
    gcn_agg1_kernel   <<<(NNODES * 32 + 255) / 256, 256>>>(b1);
    gcn_gemm2_kernel  <<<NNODES / 16, 256>>>(W2);
    gcn_agg2_kernel   <<<(NNODES * 32 + 255) / 256, 256>>>(b2, out);
}

// round 6
// speedup vs baseline: 1.0713x; 1.0713x over previous
#include <cuda_runtime.h>

#define NNODES 100000
#define NP 100224               // padded node count (multiple of 32, >= NNODES+127)
#define NEDGES 1600000
#define F0 128
#define F1 64
#define F2 16
#define NB1 ((NNODES + 255) / 256)   // 391 scan blocks

typedef unsigned long long ull;

// Scratch (device globals: allocation-free, graph-safe)
__device__ float g_xT  [F0 * NP];       // x transposed (k-major), padded
__device__ float g_dinv[NNODES];
__device__ float g_h1  [NNODES * F1];   // h~ = (x@W1)*dinv[row]
__device__ float g_t   [NNODES * F1];   // activated layer-1 output
__device__ float g_h2  [NNODES * F2];   // h~2 = (t@W2)*dinv[row]
// dst-CSR scratch
__device__ int   g_hist  [NNODES];      // in-degree (dst)
__device__ int   g_off   [NNODES];
__device__ int   g_rowptr[NNODES];
__device__ int   g_cursor[NNODES];
__device__ int   g_bsum  [512];
__device__ int   g_csr   [NEDGES];      // src ids grouped by dst

// ---------------------------------------------------------------------------
// f32x2 packed helpers (sm_103a FFMA2 — only reachable via PTX)
// ---------------------------------------------------------------------------
__device__ __forceinline__ ull pack2(float lo, float hi) {
    ull r; asm("mov.b64 %0, {%1, %2};" : "=l"(r) : "f"(lo), "f"(hi)); return r;
}
__device__ __forceinline__ void unpack2(ull v, float& lo, float& hi) {
    asm("mov.b64 {%0, %1}, %2;" : "=f"(lo), "=f"(hi) : "l"(v));
}
__device__ __forceinline__ void fma2(ull& acc, ull a, ull b) {
    asm("fma.rn.f32x2 %0, %1, %2, %0;" : "+l"(acc) : "l"(a), "l"(b));
}
__device__ __forceinline__ ull mul2(ull a, ull b) {
    ull r; asm("mul.rn.f32x2 %0, %1, %2;" : "=l"(r) : "l"(a), "l"(b)); return r;
}

// ---------------------------------------------------------------------------
// 1. Transpose x -> g_xT (k-major), zero-pad rows [NNODES, NP)
// Block 32x8, tile 32x32, grid (NP/32, F0/32). Coalesced both sides.
// ---------------------------------------------------------------------------
__global__ void gcn_transpose_kernel(const float* __restrict__ x) {
    __shared__ float tile[32][33];
    int v0 = blockIdx.x * 32, k0 = blockIdx.y * 32;
    int tx = threadIdx.x, ty = threadIdx.y;
#pragma unroll
    for (int j = 0; j < 32; j += 8) {
        int v = v0 + ty + j;
        tile[ty + j][tx] = (v < NNODES) ? x[v * F0 + k0 + tx] : 0.f;
    }
    __syncthreads();
#pragma unroll
    for (int j = 0; j < 32; j += 8)
        g_xT[(k0 + ty + j) * NP + v0 + tx] = tile[tx][ty + j];
}

// ---------------------------------------------------------------------------
// 2. Init: zero dst histogram
// ---------------------------------------------------------------------------
__global__ void gcn_init_kernel() {
    int i = blockIdx.x * blockDim.x + threadIdx.x;
    if (i < NNODES) g_hist[i] = 0;
}

// ---------------------------------------------------------------------------
// 3. In-degree histogram over dst (deg = 1 + hist)
// ---------------------------------------------------------------------------
__global__ void gcn_hist_kernel(const int* __restrict__ dst) {
    int e = blockIdx.x * blockDim.x + threadIdx.x;
    if (e < NEDGES) atomicAdd(&g_hist[dst[e]], 1);
}

// ---------------------------------------------------------------------------
// 4. GEMM1: h1[v,:] = (x[v,:] @ W1) * dinv[v],  dinv computed inline.
// Row-pair FFMA2 from k-major x:
//   xs[k][r]  : plain floats, pitch 132 — row-pairs are free halves of
//               ulonglong2 LDS (address depends only on ty -> broadcast)
//   wd[k][c]  : (W,W) dup as ull, cols strided 16 -> each LDS.64 = 128B = 1wf
// Thread tile 8 rows x 4 cols = 16 FMA2/k, zero movs. 256 thr, BM=128.
// Staging reads g_xT fully coalesced (k-rows contiguous).
// ---------------------------------------------------------------------------
#define BM 128
#define KC 64                  // k-chunk
#define PX 132                 // xs pitch in floats (16B-aligned rows)
extern __shared__ char s_g1_raw[];

__global__ void __launch_bounds__(256, 2) gcn_gemm1_kernel(
        const float* __restrict__ W1) {
    ull*   wd = (ull*)s_g1_raw;                    // F0*F1 ull = 64 KB
    float* xs = (float*)(s_g1_raw + F0 * F1 * 8);  // KC*PX floats = 33.8 KB
    int tid = threadIdx.x;
    int row0 = blockIdx.x * BM;

    // Stage duplicated W once: wd[k*64 + c] = (W[k][c], W[k][c])
    for (int i = tid; i < F0 * F1; i += 256) {
        float w = W1[i];
        wd[i] = pack2(w, w);
    }

    int ty = tid >> 4;          // 0..15 -> rows 8*ty..8*ty+7
    int tx = tid & 15;          // cols: tx, tx+16, tx+32, tx+48

    ull acc[4][4];              // [rowpair p][colblk c]
#pragma unroll
    for (int p = 0; p < 4; p++)
#pragma unroll
        for (int c = 0; c < 4; c++) acc[p][c] = 0ull;

    const float* xbase = xs + 8 * ty;

    for (int kc = 0; kc < F0; kc += KC) {
        __syncthreads();
        // Stage xs: 2048 float4 tasks (k-row x 32 segs), coalesced LDG + STS
        for (int i = tid; i < KC * 32; i += 256) {
            int k = i >> 5, seg = i & 31;
            float4 v = *(const float4*)&g_xT[(kc + k) * NP + row0 + seg * 4];
            *(float4*)&xs[k * PX + seg * 4] = v;
        }
        __syncthreads();

#pragma unroll 8
        for (int kk = 0; kk < KC; kk++) {
            int k = kc + kk;
            ulonglong2 X01 = *(const ulonglong2*)(xbase + kk * PX);     // rows 0-3
            ulonglong2 X23 = *(const ulonglong2*)(xbase + kk * PX + 4); // rows 4-7
            ull w0 = wd[k * F1 + tx];
            ull w1 = wd[k * F1 + tx + 16];
            ull w2 = wd[k * F1 + tx + 32];
            ull w3 = wd[k * F1 + tx + 48];
            ull px[4] = { X01.x, X01.y, X23.x, X23.y };
#pragma unroll
            for (int p = 0; p < 4; p++) {
                fma2(acc[p][0], px[p], w0);
                fma2(acc[p][1], px[p], w1);
                fma2(acc[p][2], px[p], w2);
                fma2(acc[p][3], px[p], w3);
            }
        }
    }

    // Epilogue: dinv inline, scale row-pairs, scalar stores (64B coalesced)
#pragma unroll
    for (int p = 0; p < 4; p++) {
        int v0 = row0 + ty * 8 + 2 * p;
        if (v0 >= NNODES) continue;
        float d0 = rsqrtf(1.0f + (float)g_hist[v0]);
        float d1 = (v0 + 1 < NNODES) ? rsqrtf(1.0f + (float)g_hist[v0 + 1]) : 0.f;
        if (tx == 0) {
            g_dinv[v0] = d0;
            if (v0 + 1 < NNODES) g_dinv[v0 + 1] = d1;
        }
        ull dd = pack2(d0, d1);
#pragma unroll
        for (int c = 0; c < 4; c++) {
            float lo, hi;
            unpack2(mul2(acc[p][c], dd), lo, hi);
            g_h1[v0 * F1 + tx + 16 * c] = lo;
            if (v0 + 1 < NNODES) g_h1[(v0 + 1) * F1 + tx + 16 * c] = hi;
        }
    }
}

// ---------------------------------------------------------------------------
// 5-7. Two-level exclusive scan of g_hist -> rowptr + cursor
// ---------------------------------------------------------------------------
__global__ void gcn_scan1_kernel() {
    __shared__ int s[256];
    int tid = threadIdx.x;
    int i = blockIdx.x * 256 + tid;
    int v = (i < NNODES) ? g_hist[i] : 0;
    s[tid] = v;
    __syncthreads();
#pragma unroll
    for (int o = 1; o < 256; o <<= 1) {
        int t = (tid >= o) ? s[tid - o] : 0;
        __syncthreads();
        s[tid] += t;
        __syncthreads();
    }
    if (i < NNODES) g_off[i] = s[tid] - v;
    if (tid == 255) g_bsum[blockIdx.x] = s[255];
}

__global__ void gcn_scan2_kernel() {
    __shared__ int s[512];
    int tid = threadIdx.x;
    int v = (tid < NB1) ? g_bsum[tid] : 0;
    s[tid] = v;
    __syncthreads();
#pragma unroll
    for (int o = 1; o < 512; o <<= 1) {
        int t = (tid >= o) ? s[tid - o] : 0;
        __syncthreads();
        s[tid] += t;
        __syncthreads();
    }
    if (tid < NB1) g_bsum[tid] = s[tid] - v;
}

__global__ void gcn_rowptr_kernel() {
    int i = blockIdx.x * blockDim.x + threadIdx.x;
    if (i < NNODES) {
        int p = g_off[i] + g_bsum[i >> 8];
        g_rowptr[i] = p;
        g_cursor[i] = p;
    }
}

// ---------------------------------------------------------------------------
// 8. Permute: group src ids by dst (CSR fill)
// ---------------------------------------------------------------------------
__global__ void gcn_permute_kernel(const int* __restrict__ src,
                                   const int* __restrict__ dst) {
    int e = blockIdx.x * blockDim.x + threadIdx.x;
    if (e < NEDGES) {
        int d = dst[e];
        int p = atomicAdd(&g_cursor[d], 1);
        g_csr[p] = src[e];
    }
}

// ---------------------------------------------------------------------------
// 9. Layer-1 aggregation + activation (warp per node, float2 per lane):
//    t[v] = leaky_relu(dinv[v] * (h1[v] + sum_{s->v} h1[s]) + b1)
// ---------------------------------------------------------------------------
__global__ void gcn_agg1_kernel(const float* __restrict__ b1) {
    int w = (blockIdx.x * blockDim.x + threadIdx.x) >> 5;
    int lane = threadIdx.x & 31;
    if (w >= NNODES) return;
    int v = w;
    int beg = g_rowptr[v];
    int len = g_hist[v];

    float2 acc = *(const float2*)&g_h1[v * F1 + lane * 2];   // self loop

    const int* __restrict__ idx = &g_csr[beg];
    int i = 0;
    for (; i + 4 <= len; i += 4) {
        int s0 = idx[i], s1 = idx[i + 1], s2 = idx[i + 2], s3 = idx[i + 3];
        float2 u0 = *(const float2*)&g_h1[s0 * F1 + lane * 2];
        float2 u1 = *(const float2*)&g_h1[s1 * F1 + lane * 2];
        float2 u2 = *(const float2*)&g_h1[s2 * F1 + lane * 2];
        float2 u3 = *(const float2*)&g_h1[s3 * F1 + lane * 2];
        acc.x += u0.x + u1.x + u2.x + u3.x;
        acc.y += u0.y + u1.y + u2.y + u3.y;
    }
    for (; i < len; i++) {
        int s = idx[i];
        float2 u = *(const float2*)&g_h1[s * F1 + lane * 2];
        acc.x += u.x; acc.y += u.y;
    }

    float dv = g_dinv[v];
    float t0 = dv * acc.x + b1[lane * 2];
    float t1 = dv * acc.y + b1[lane * 2 + 1];
    t0 = t0 >= 0.f ? t0 : 0.2f * t0;
    t1 = t1 >= 0.f ? t1 : 0.2f * t1;
    *(float2*)&g_t[v * F1 + lane * 2] = make_float2(t0, t1);
}

// ---------------------------------------------------------------------------
// 10. GEMM2: h2[v,:] = (t[v,:] @ W2) * dinv[v]    [N,64]x[64,16]
// ---------------------------------------------------------------------------
__global__ void gcn_gemm2_kernel(const float* __restrict__ W2) {
    __shared__ __align__(16) float W2s[F1 * F2];
    __shared__ __align__(16) float ts[16][F1];
    int tid = threadIdx.x;
    for (int i = tid; i < F1 * F2; i += 256) W2s[i] = W2[i];

    int v0 = blockIdx.x * 16;
    for (int i = tid; i < 16 * 16; i += 256) {
        int r = i >> 4, q = i & 15;
        *(float4*)&ts[r][q * 4] = *(const float4*)&g_t[(v0 + r) * F1 + q * 4];
    }
    __syncthreads();

    int r = tid >> 4;
    int m = tid & 15;
    int v = v0 + r;
    float acc = 0.f;
#pragma unroll
    for (int j = 0; j < F1; j++) acc += ts[r][j] * W2s[j * F2 + m];
    g_h2[v * F2 + m] = acc * g_dinv[v];
}

// ---------------------------------------------------------------------------
// 11. Layer-2 aggregation + log_softmax (warp per node)
// ---------------------------------------------------------------------------
__global__ void gcn_agg2_kernel(const float* __restrict__ b2,
                                float* __restrict__ out) {
    int w = (blockIdx.x * blockDim.x + threadIdx.x) >> 5;
    int lane = threadIdx.x & 31;
    if (w >= NNODES) return;
    int v = w;
    int beg = g_rowptr[v];
    int len = g_hist[v];
    int f = lane & 15;

    float acc = 0.f;
    const int* __restrict__ idx = &g_csr[beg];
    for (int i = (lane >> 4); i < len; i += 2) {
        int s = idx[i];
        acc += g_h2[s * F2 + f];
    }
    acc += __shfl_down_sync(0xffffffffu, acc, 16);

    float dv = g_dinv[v];
    float t = dv * (acc + g_h2[v * F2 + f]) + b2[f];

    float mx = t;
#pragma unroll
    for (int o = 8; o >= 1; o >>= 1)
        mx = fmaxf(mx, __shfl_xor_sync(0xffffffffu, mx, o));
    float ex = expf(t - mx);
    float sum = ex;
#pragma unroll
    for (int o = 8; o >= 1; o >>= 1)
        sum += __shfl_xor_sync(0xffffffffu, sum, o);
    float lse = mx + logf(sum);

    if (lane < 16) out[v * F2 + f] = t - lse;
}

// ---------------------------------------------------------------------------
// Launch
// ---------------------------------------------------------------------------
extern "C" void kernel_launch(void* const* d_in, const int* in_sizes, int n_in,
                              void* d_out, int out_size) {
    const float* x  = (const float*)d_in[0];
    const int*   ei = (const int*)  d_in[1];
    const float* W1 = (const float*)d_in[2];
    const float* b1 = (const float*)d_in[3];
    const float* W2 = (const float*)d_in[4];
    const float* b2 = (const float*)d_in[5];
    float* out = (float*)d_out;

    const int* src = ei;
    const int* dst = ei + NEDGES;

    const int gemm1_smem = F0 * F1 * 8 + KC * PX * 4;   // 64KB + 33.8KB = 97.8KB
    cudaFuncSetAttribute(gcn_gemm1_kernel,
                         cudaFuncAttributeMaxDynamicSharedMemorySize, gemm1_smem);

    dim3 tgrid(NP / 32, F0 / 32);
    gcn_transpose_kernel<<<tgrid, dim3(32, 8)>>>(x);
    gcn_init_kernel     <<<(NNODES + 255) / 256, 256>>>();
    gcn_hist_kernel     <<<(NEDGES + 255) / 256, 256>>>(dst);
    gcn_gemm1_kernel    <<<(NNODES + BM - 1) / BM, 256, gemm1_smem>>>(W1);
    gcn_scan1_kernel    <<<NB1, 256>>>();
    gcn_scan2_kernel    <<<1, 512>>>();
    gcn_rowptr_kernel   <<<(NNODES + 255) / 256, 256>>>();
    gcn_permute_kernel  <<<(NEDGES + 255) / 256, 256>>>(src, dst);
    gcn_agg1_kernel     <<<(NNODES * 32 + 255) / 256, 256>>>(b1);
    gcn_gemm2_kernel    <<<NNODES / 16, 256>>>(W2);
    gcn_agg2_kernel     <<<(NNODES * 32 + 255) / 256, 256>>>(b2, out);
}

// round 8
// speedup vs baseline: 1.0972x; 1.0241x over previous
#include <cuda_runtime.h>
#include <cuda_fp16.h>

#define NNODES 100000
#define NP 100224               // padded node count (multiple of 32, >= NNODES+127)
#define NEDGES 1600000
#define F0 128
#define F1 64
#define F2 16
#define NB1 ((NNODES + 255) / 256)   // 391 scan blocks

typedef unsigned long long ull;

// Scratch (device globals: allocation-free, graph-safe)
__device__ float  g_xT  [F0 * NP];       // x transposed (k-major), padded
__device__ float  g_dinv[NNODES];
__device__ __half g_h1h [NNODES * F1];   // h~ = (x@W1)*dinv[row], fp16 for gathers
__device__ float  g_t   [NNODES * F1];   // activated layer-1 output
__device__ float  g_h2  [NNODES * F2];   // h~2 = (t@W2)*dinv[row]
// dst-CSR scratch
__device__ int    g_hist  [NNODES];      // in-degree (dst)
__device__ int    g_off   [NNODES];
__device__ int    g_rowptr[NNODES];
__device__ int    g_cursor[NNODES];
__device__ int    g_bsum  [512];
__device__ int    g_csr   [NEDGES];      // src ids grouped by dst

// ---------------------------------------------------------------------------
// f32x2 packed helpers (sm_103a FFMA2 — only reachable via PTX)
// ---------------------------------------------------------------------------
__device__ __forceinline__ ull pack2(float lo, float hi) {
    ull r; asm("mov.b64 %0, {%1, %2};" : "=l"(r) : "f"(lo), "f"(hi)); return r;
}
__device__ __forceinline__ void unpack2(ull v, float& lo, float& hi) {
    asm("mov.b64 {%0, %1}, %2;" : "=f"(lo), "=f"(hi) : "l"(v));
}
__device__ __forceinline__ void fma2(ull& acc, ull a, ull b) {
    asm("fma.rn.f32x2 %0, %1, %2, %0;" : "+l"(acc) : "l"(a), "l"(b));
}
__device__ __forceinline__ ull mul2(ull a, ull b) {
    ull r; asm("mul.rn.f32x2 %0, %1, %2;" : "=l"(r) : "l"(a), "l"(b)); return r;
}

// ---------------------------------------------------------------------------
// 1. Transpose x -> g_xT (k-major), zero-pad rows [NNODES, NP)
// ---------------------------------------------------------------------------
__global__ void gcn_transpose_kernel(const float* __restrict__ x) {
    __shared__ float tile[32][33];
    int v0 = blockIdx.x * 32, k0 = blockIdx.y * 32;
    int tx = threadIdx.x, ty = threadIdx.y;
#pragma unroll
    for (int j = 0; j < 32; j += 8) {
        int v = v0 + ty + j;
        tile[ty + j][tx] = (v < NNODES) ? x[v * F0 + k0 + tx] : 0.f;
    }
    __syncthreads();
#pragma unroll
    for (int j = 0; j < 32; j += 8)
        g_xT[(k0 + ty + j) * NP + v0 + tx] = tile[tx][ty + j];
}

// ---------------------------------------------------------------------------
// 2. Init: zero dst histogram
// ---------------------------------------------------------------------------
__global__ void gcn_init_kernel() {
    int i = blockIdx.x * blockDim.x + threadIdx.x;
    if (i < NNODES) g_hist[i] = 0;
}

// ---------------------------------------------------------------------------
// 3. In-degree histogram over dst (deg = 1 + hist)
// ---------------------------------------------------------------------------
__global__ void gcn_hist_kernel(const int* __restrict__ dst) {
    int e = blockIdx.x * blockDim.x + threadIdx.x;
    if (e < NEDGES) atomicAdd(&g_hist[dst[e]], 1);
}

// ---------------------------------------------------------------------------
// 4. GEMM1: h1[v,:] = (x[v,:] @ W1) * dinv[v],  dinv computed inline.
// Row-pair FFMA2 from k-major x. W AND x staged per k-chunk (65.8KB smem)
// so 3 blocks/SM fit -> 24 warps/SM for latency hiding.
// Thread tile 8 rows x 4 cols = 16 FMA2/k, zero movs. 256 thr, BM=128.
// ---------------------------------------------------------------------------
#define BM 128
#define KC 64                  // k-chunk
#define PX 132                 // xs pitch in floats (16B-aligned rows)
extern __shared__ char s_g1_raw[];

__global__ void __launch_bounds__(256, 3) gcn_gemm1_kernel(
        const float* __restrict__ x, const float* __restrict__ W1) {
    ull*   wd = (ull*)s_g1_raw;                    // KC*F1 ull = 32 KB (per chunk)
    float* xs = (float*)(s_g1_raw + KC * F1 * 8);  // KC*PX floats = 33.8 KB
    int tid = threadIdx.x;
    int row0 = blockIdx.x * BM;

    int ty = tid >> 4;          // 0..15 -> rows 8*ty..8*ty+7
    int tx = tid & 15;          // cols: tx, tx+16, tx+32, tx+48

    ull acc[4][4];              // [rowpair p][colblk c]
#pragma unroll
    for (int p = 0; p < 4; p++)
#pragma unroll
        for (int c = 0; c < 4; c++) acc[p][c] = 0ull;

    const float* xbase = xs + 8 * ty;

    for (int kc = 0; kc < F0; kc += KC) {
        __syncthreads();
        // Stage duplicated W chunk: wd[k*64 + c] = (W[kc+k][c], W[kc+k][c])
        for (int i = tid; i < KC * F1; i += 256) {
            float w = W1[kc * F1 + i];
            wd[i] = pack2(w, w);
        }
        // Stage xs: KC*32 float4 tasks, coalesced LDG + STS
        for (int i = tid; i < KC * 32; i += 256) {
            int k = i >> 5, seg = i & 31;
            float4 v = *(const float4*)&g_xT[(kc + k) * NP + row0 + seg * 4];
            *(float4*)&xs[k * PX + seg * 4] = v;
        }
        __syncthreads();

#pragma unroll 8
        for (int kk = 0; kk < KC; kk++) {
            ulonglong2 X01 = *(const ulonglong2*)(xbase + kk * PX);     // rows 0-3
            ulonglong2 X23 = *(const ulonglong2*)(xbase + kk * PX + 4); // rows 4-7
            ull w0 = wd[kk * F1 + tx];
            ull w1 = wd[kk * F1 + tx + 16];
            ull w2 = wd[kk * F1 + tx + 32];
            ull w3 = wd[kk * F1 + tx + 48];
            ull px[4] = { X01.x, X01.y, X23.x, X23.y };
#pragma unroll
            for (int p = 0; p < 4; p++) {
                fma2(acc[p][0], px[p], w0);
                fma2(acc[p][1], px[p], w1);
                fma2(acc[p][2], px[p], w2);
                fma2(acc[p][3], px[p], w3);
            }
        }
    }

    // Epilogue: dinv inline, scale row-pairs, store fp16
#pragma unroll
    for (int p = 0; p < 4; p++) {
        int v0 = row0 + ty * 8 + 2 * p;
        if (v0 >= NNODES) continue;
        float d0 = rsqrtf(1.0f + (float)g_hist[v0]);
        float d1 = (v0 + 1 < NNODES) ? rsqrtf(1.0f + (float)g_hist[v0 + 1]) : 0.f;
        if (tx == 0) {
            g_dinv[v0] = d0;
            if (v0 + 1 < NNODES) g_dinv[v0 + 1] = d1;
        }
        ull dd = pack2(d0, d1);
#pragma unroll
        for (int c = 0; c < 4; c++) {
            float lo, hi;
            unpack2(mul2(acc[p][c], dd), lo, hi);
            g_h1h[v0 * F1 + tx + 16 * c] = __float2half(lo);
            if (v0 + 1 < NNODES)
                g_h1h[(v0 + 1) * F1 + tx + 16 * c] = __float2half(hi);
        }
    }
}

// ---------------------------------------------------------------------------
// 5-7. Two-level exclusive scan of g_hist -> rowptr + cursor
// ---------------------------------------------------------------------------
__global__ void gcn_scan1_kernel() {
    __shared__ int s[256];
    int tid = threadIdx.x;
    int i = blockIdx.x * 256 + tid;
    int v = (i < NNODES) ? g_hist[i] : 0;
    s[tid] = v;
    __syncthreads();
#pragma unroll
    for (int o = 1; o < 256; o <<= 1) {
        int t = (tid >= o) ? s[tid - o] : 0;
        __syncthreads();
        s[tid] += t;
        __syncthreads();
    }
    if (i < NNODES) g_off[i] = s[tid] - v;
    if (tid == 255) g_bsum[blockIdx.x] = s[255];
}

__global__ void gcn_scan2_kernel() {
    __shared__ int s[512];
    int tid = threadIdx.x;
    int v = (tid < NB1) ? g_bsum[tid] : 0;
    s[tid] = v;
    __syncthreads();
#pragma unroll
    for (int o = 1; o < 512; o <<= 1) {
        int t = (tid >= o) ? s[tid - o] : 0;
        __syncthreads();
        s[tid] += t;
        __syncthreads();
    }
    if (tid < NB1) g_bsum[tid] = s[tid] - v;
}

__global__ void gcn_rowptr_kernel() {
    int i = blockIdx.x * blockDim.x + threadIdx.x;
    if (i < NNODES) {
        int p = g_off[i] + g_bsum[i >> 8];
        g_rowptr[i] = p;
        g_cursor[i] = p;
    }
}

// ---------------------------------------------------------------------------
// 8. Permute: group src ids by dst (CSR fill)
// ---------------------------------------------------------------------------
__global__ void gcn_permute_kernel(const int* __restrict__ src,
                                   const int* __restrict__ dst) {
    int e = blockIdx.x * blockDim.x + threadIdx.x;
    if (e < NEDGES) {
        int d = dst[e];
        int p = atomicAdd(&g_cursor[d], 1);
        g_csr[p] = src[e];
    }
}

// ---------------------------------------------------------------------------
// 9. Layer-1 aggregation + activation (warp per node, half2 per lane):
//    t[v] = leaky_relu(dinv[v] * (h1[v] + sum_{s->v} h1[s]) + b1)
// Gathers read fp16 rows (128B/edge), accumulate fp32.
// ---------------------------------------------------------------------------
__global__ void gcn_agg1_kernel(const float* __restrict__ b1) {
    int w = (blockIdx.x * blockDim.x + threadIdx.x) >> 5;
    int lane = threadIdx.x & 31;
    if (w >= NNODES) return;
    int v = w;
    int beg = g_rowptr[v];
    int len = g_hist[v];

    float2 acc = __half22float2(*(const __half2*)&g_h1h[v * F1 + lane * 2]);

    const int* __restrict__ idx = &g_csr[beg];
    int i = 0;
    for (; i + 4 <= len; i += 4) {
        int s0 = idx[i], s1 = idx[i + 1], s2 = idx[i + 2], s3 = idx[i + 3];
        float2 u0 = __half22float2(*(const __half2*)&g_h1h[s0 * F1 + lane * 2]);
        float2 u1 = __half22float2(*(const __half2*)&g_h1h[s1 * F1 + lane * 2]);
        float2 u2 = __half22float2(*(const __half2*)&g_h1h[s2 * F1 + lane * 2]);
        float2 u3 = __half22float2(*(const __half2*)&g_h1h[s3 * F1 + lane * 2]);
        acc.x += u0.x + u1.x + u2.x + u3.x;
        acc.y += u0.y + u1.y + u2.y + u3.y;
    }
    for (; i < len; i++) {
        int s = idx[i];
        float2 u = __half22float2(*(const __half2*)&g_h1h[s * F1 + lane * 2]);
        acc.x += u.x; acc.y += u.y;
    }

    float dv = g_dinv[v];
    float t0 = dv * acc.x + b1[lane * 2];
    float t1 = dv * acc.y + b1[lane * 2 + 1];
    t0 = t0 >= 0.f ? t0 : 0.2f * t0;
    t1 = t1 >= 0.f ? t1 : 0.2f * t1;
    *(float2*)&g_t[v * F1 + lane * 2] = make_float2(t0, t1);
}

// ---------------------------------------------------------------------------
// 10. GEMM2: h2[v,:] = (t[v,:] @ W2) * dinv[v]    [N,64]x[64,16]
// ---------------------------------------------------------------------------
__global__ void gcn_gemm2_kernel(const float* __restrict__ W2) {
    __shared__ __align__(16) float W2s[F1 * F2];
    __shared__ __align__(16) float ts[16][F1];
    int tid = threadIdx.x;
    for (int i = tid; i < F1 * F2; i += 256) W2s[i] = W2[i];

    int v0 = blockIdx.x * 16;
    for (int i = tid; i < 16 * 16; i += 256) {
        int r = i >> 4, q = i & 15;
        *(float4*)&ts[r][q * 4] = *(const float4*)&g_t[(v0 + r) * F1 + q * 4];
    }
    __syncthreads();

    int r = tid >> 4;
    int m = tid & 15;
    int v = v0 + r;
    float acc = 0.f;
#pragma unroll
    for (int j = 0; j < F1; j++) acc += ts[r][j] * W2s[j * F2 + m];
    g_h2[v * F2 + m] = acc * g_dinv[v];
}

// ---------------------------------------------------------------------------
// 11. Layer-2 aggregation + log_softmax (warp per node)
// ---------------------------------------------------------------------------
__global__ void gcn_agg2_kernel(const float* __restrict__ b2,
                                float* __restrict__ out) {
    int w = (blockIdx.x * blockDim.x + threadIdx.x) >> 5;
    int lane = threadIdx.x & 31;
    if (w >= NNODES) return;
    int v = w;
    int beg = g_rowptr[v];
    int len = g_hist[v];
    int f = lane & 15;

    float acc = 0.f;
    const int* __restrict__ idx = &g_csr[beg];
    for (int i = (lane >> 4); i < len; i += 2) {
        int s = idx[i];
        acc += g_h2[s * F2 + f];
    }
    acc += __shfl_down_sync(0xffffffffu, acc, 16);

    float dv = g_dinv[v];
    float t = dv * (acc + g_h2[v * F2 + f]) + b2[f];

    float mx = t;
#pragma unroll
    for (int o = 8; o >= 1; o >>= 1)
        mx = fmaxf(mx, __shfl_xor_sync(0xffffffffu, mx, o));
    float ex = expf(t - mx);
    float sum = ex;
#pragma unroll
    for (int o = 8; o >= 1; o >>= 1)
        sum += __shfl_xor_sync(0xffffffffu, sum, o);
    float lse = mx + logf(sum);

    if (lane < 16) out[v * F2 + f] = t - lse;
}

// ---------------------------------------------------------------------------
// Launch
// ---------------------------------------------------------------------------
extern "C" void kernel_launch(void* const* d_in, const int* in_sizes, int n_in,
                              void* d_out, int out_size) {
    const float* x  = (const float*)d_in[0];
    const int*   ei = (const int*)  d_in[1];
    const float* W1 = (const float*)d_in[2];
    const float* b1 = (const float*)d_in[3];
    const float* W2 = (const float*)d_in[4];
    const float* b2 = (const float*)d_in[5];
    float* out = (float*)d_out;

    const int* src = ei;
    const int* dst = ei + NEDGES;

    const int gemm1_smem = KC * F1 * 8 + KC * PX * 4;   // 32KB + 33.8KB = 65.8KB
    cudaFuncSetAttribute(gcn_gemm1_kernel,
                         cudaFuncAttributeMaxDynamicSharedMemorySize, gemm1_smem);

    dim3 tgrid(NP / 32, F0 / 32);
    gcn_transpose_kernel<<<tgrid, dim3(32, 8)>>>(x);
    gcn_init_kernel     <<<(NNODES + 255) / 256, 256>>>();
    gcn_hist_kernel     <<<(NEDGES + 255) / 256, 256>>>(dst);
    gcn_gemm1_kernel    <<<(NNODES + BM - 1) / BM, 256, gemm1_smem>>>(x, W1);
    gcn_scan1_kernel    <<<NB1, 256>>>();
    gcn_scan2_kernel    <<<1, 512>>>();
    gcn_rowptr_kernel   <<<(NNODES + 255) / 256, 256>>>();
    gcn_permute_kernel  <<<(NEDGES + 255) / 256, 256>>>(src, dst);
    gcn_agg1_kernel     <<<(NNODES * 32 + 255) / 256, 256>>>(b1);
    gcn_gemm2_kernel    <<<NNODES / 16, 256>>>(W2);
    gcn_agg2_kernel     <<<(NNODES * 32 + 255) / 256, 256>>>(b2, out);
}

// round 9
// speedup vs baseline: 1.1568x; 1.0544x over previous
#include <cuda_runtime.h>
#include <cuda_fp16.h>

#define NNODES 100000
#define NP 100224               // padded node count (multiple of 32, >= NNODES+127)
#define NEDGES 1600000
#define F0 128
#define F1 64
#define F2 16
#define NB1 ((NNODES + 255) / 256)   // 391 scan blocks

typedef unsigned long long ull;

// Scratch (device globals: allocation-free, graph-safe)
__device__ float  g_xT  [F0 * NP];       // x transposed (k-major), padded
__device__ float  g_dinv[NNODES];
__device__ __half g_h1h [NNODES * F1];   // h~ = (x@W1)*dinv[row], fp16 for gathers
__device__ float  g_t   [NNODES * F1];   // activated layer-1 output
__device__ float  g_h2  [NNODES * F2];   // h~2 = (t@W2)*dinv[row]
// dst-CSR scratch
__device__ int    g_hist  [NNODES];      // in-degree (dst)
__device__ int    g_off   [NNODES];
__device__ int    g_rowptr[NNODES];
__device__ int    g_cursor[NNODES];
__device__ int    g_bsum  [512];
__device__ int    g_csr   [NEDGES];      // src ids grouped by dst

// ---------------------------------------------------------------------------
// f32x2 packed helpers (sm_103a FFMA2 — only reachable via PTX)
// ---------------------------------------------------------------------------
__device__ __forceinline__ ull pack2(float lo, float hi) {
    ull r; asm("mov.b64 %0, {%1, %2};" : "=l"(r) : "f"(lo), "f"(hi)); return r;
}
__device__ __forceinline__ void unpack2(ull v, float& lo, float& hi) {
    asm("mov.b64 {%0, %1}, %2;" : "=f"(lo), "=f"(hi) : "l"(v));
}
__device__ __forceinline__ void fma2(ull& acc, ull a, ull b) {
    asm("fma.rn.f32x2 %0, %1, %2, %0;" : "+l"(acc) : "l"(a), "l"(b));
}
__device__ __forceinline__ ull mul2(ull a, ull b) {
    ull r; asm("mul.rn.f32x2 %0, %1, %2;" : "=l"(r) : "l"(a), "l"(b)); return r;
}

// ---------------------------------------------------------------------------
// Transpose x -> g_xT (k-major), zero-pad rows [NNODES, NP)
// ---------------------------------------------------------------------------
__global__ void gcn_transpose_kernel(const float* __restrict__ x) {
    __shared__ float tile[32][33];
    int v0 = blockIdx.x * 32, k0 = blockIdx.y * 32;
    int tx = threadIdx.x, ty = threadIdx.y;
#pragma unroll
    for (int j = 0; j < 32; j += 8) {
        int v = v0 + ty + j;
        tile[ty + j][tx] = (v < NNODES) ? x[v * F0 + k0 + tx] : 0.f;
    }
    __syncthreads();
#pragma unroll
    for (int j = 0; j < 32; j += 8)
        g_xT[(k0 + ty + j) * NP + v0 + tx] = tile[tx][ty + j];
}

// ---------------------------------------------------------------------------
// Init: zero dst histogram
// ---------------------------------------------------------------------------
__global__ void gcn_init_kernel() {
    int i = blockIdx.x * blockDim.x + threadIdx.x;
    if (i < NNODES) g_hist[i] = 0;
}

// ---------------------------------------------------------------------------
// In-degree histogram over dst (deg = 1 + hist)
// ---------------------------------------------------------------------------
__global__ void gcn_hist_kernel(const int* __restrict__ dst) {
    int e = blockIdx.x * blockDim.x + threadIdx.x;
    if (e < NEDGES) atomicAdd(&g_hist[dst[e]], 1);
}

// ---------------------------------------------------------------------------
// GEMM1: h1[v,:] = (x[v,:] @ W1) * dinv[v],  dinv computed inline from hist.
// Row-pair FFMA2 from k-major x. W AND x staged per k-chunk (65.8KB smem),
// 3 blocks/SM -> 24 warps/SM. Thread tile 8 rows x 4 cols, zero movs.
// ---------------------------------------------------------------------------
#define BM 128
#define KC 64                  // k-chunk
#define PX 132                 // xs pitch in floats (16B-aligned rows)
extern __shared__ char s_g1_raw[];

__global__ void __launch_bounds__(256, 3) gcn_gemm1_kernel(
        const float* __restrict__ W1) {
    ull*   wd = (ull*)s_g1_raw;                    // KC*F1 ull = 32 KB (per chunk)
    float* xs = (float*)(s_g1_raw + KC * F1 * 8);  // KC*PX floats = 33.8 KB
    int tid = threadIdx.x;
    int row0 = blockIdx.x * BM;

    int ty = tid >> 4;          // 0..15 -> rows 8*ty..8*ty+7
    int tx = tid & 15;          // cols: tx, tx+16, tx+32, tx+48

    ull acc[4][4];              // [rowpair p][colblk c]
#pragma unroll
    for (int p = 0; p < 4; p++)
#pragma unroll
        for (int c = 0; c < 4; c++) acc[p][c] = 0ull;

    const float* xbase = xs + 8 * ty;

    for (int kc = 0; kc < F0; kc += KC) {
        __syncthreads();
        // Stage duplicated W chunk: wd[k*64 + c] = (W[kc+k][c], W[kc+k][c])
        for (int i = tid; i < KC * F1; i += 256) {
            float w = W1[kc * F1 + i];
            wd[i] = pack2(w, w);
        }
        // Stage xs: KC*32 float4 tasks, coalesced LDG + STS
        for (int i = tid; i < KC * 32; i += 256) {
            int k = i >> 5, seg = i & 31;
            float4 v = *(const float4*)&g_xT[(kc + k) * NP + row0 + seg * 4];
            *(float4*)&xs[k * PX + seg * 4] = v;
        }
        __syncthreads();

#pragma unroll 8
        for (int kk = 0; kk < KC; kk++) {
            ulonglong2 X01 = *(const ulonglong2*)(xbase + kk * PX);     // rows 0-3
            ulonglong2 X23 = *(const ulonglong2*)(xbase + kk * PX + 4); // rows 4-7
            ull w0 = wd[kk * F1 + tx];
            ull w1 = wd[kk * F1 + tx + 16];
            ull w2 = wd[kk * F1 + tx + 32];
            ull w3 = wd[kk * F1 + tx + 48];
            ull px[4] = { X01.x, X01.y, X23.x, X23.y };
#pragma unroll
            for (int p = 0; p < 4; p++) {
                fma2(acc[p][0], px[p], w0);
                fma2(acc[p][1], px[p], w1);
                fma2(acc[p][2], px[p], w2);
                fma2(acc[p][3], px[p], w3);
            }
        }
    }

    // Epilogue: dinv inline, scale row-pairs, store fp16
#pragma unroll
    for (int p = 0; p < 4; p++) {
        int v0 = row0 + ty * 8 + 2 * p;
        if (v0 >= NNODES) continue;
        float d0 = rsqrtf(1.0f + (float)g_hist[v0]);
        float d1 = (v0 + 1 < NNODES) ? rsqrtf(1.0f + (float)g_hist[v0 + 1]) : 0.f;
        if (tx == 0) {
            g_dinv[v0] = d0;
            if (v0 + 1 < NNODES) g_dinv[v0 + 1] = d1;
        }
        ull dd = pack2(d0, d1);
#pragma unroll
        for (int c = 0; c < 4; c++) {
            float lo, hi;
            unpack2(mul2(acc[p][c], dd), lo, hi);
            g_h1h[v0 * F1 + tx + 16 * c] = __float2half(lo);
            if (v0 + 1 < NNODES)
                g_h1h[(v0 + 1) * F1 + tx + 16 * c] = __float2half(hi);
        }
    }
}

// ---------------------------------------------------------------------------
// Two-level exclusive scan of g_hist -> rowptr + cursor
// ---------------------------------------------------------------------------
__global__ void gcn_scan1_kernel() {
    __shared__ int s[256];
    int tid = threadIdx.x;
    int i = blockIdx.x * 256 + tid;
    int v = (i < NNODES) ? g_hist[i] : 0;
    s[tid] = v;
    __syncthreads();
#pragma unroll
    for (int o = 1; o < 256; o <<= 1) {
        int t = (tid >= o) ? s[tid - o] : 0;
        __syncthreads();
        s[tid] += t;
        __syncthreads();
    }
    if (i < NNODES) g_off[i] = s[tid] - v;
    if (tid == 255) g_bsum[blockIdx.x] = s[255];
}

__global__ void gcn_scan2_kernel() {
    __shared__ int s[512];
    int tid = threadIdx.x;
    int v = (tid < NB1) ? g_bsum[tid] : 0;
    s[tid] = v;
    __syncthreads();
#pragma unroll
    for (int o = 1; o < 512; o <<= 1) {
        int t = (tid >= o) ? s[tid - o] : 0;
        __syncthreads();
        s[tid] += t;
        __syncthreads();
    }
    if (tid < NB1) g_bsum[tid] = s[tid] - v;
}

__global__ void gcn_rowptr_kernel() {
    int i = blockIdx.x * blockDim.x + threadIdx.x;
    if (i < NNODES) {
        int p = g_off[i] + g_bsum[i >> 8];
        g_rowptr[i] = p;
        g_cursor[i] = p;
    }
}

// ---------------------------------------------------------------------------
// Permute: group src ids by dst (CSR fill)
// ---------------------------------------------------------------------------
__global__ void gcn_permute_kernel(const int* __restrict__ src,
                                   const int* __restrict__ dst) {
    int e = blockIdx.x * blockDim.x + threadIdx.x;
    if (e < NEDGES) {
        int d = dst[e];
        int p = atomicAdd(&g_cursor[d], 1);
        g_csr[p] = src[e];
    }
}

// ---------------------------------------------------------------------------
// Layer-1 aggregation + activation (warp per node, half2 per lane):
//    t[v] = leaky_relu(dinv[v] * (h1[v] + sum_{s->v} h1[s]) + b1)
// ---------------------------------------------------------------------------
__global__ void gcn_agg1_kernel(const float* __restrict__ b1) {
    int w = (blockIdx.x * blockDim.x + threadIdx.x) >> 5;
    int lane = threadIdx.x & 31;
    if (w >= NNODES) return;
    int v = w;
    int beg = g_rowptr[v];
    int len = g_hist[v];

    float2 acc = __half22float2(*(const __half2*)&g_h1h[v * F1 + lane * 2]);

    const int* __restrict__ idx = &g_csr[beg];
    int i = 0;
    for (; i + 4 <= len; i += 4) {
        int s0 = idx[i], s1 = idx[i + 1], s2 = idx[i + 2], s3 = idx[i + 3];
        float2 u0 = __half22float2(*(const __half2*)&g_h1h[s0 * F1 + lane * 2]);
        float2 u1 = __half22float2(*(const __half2*)&g_h1h[s1 * F1 + lane * 2]);
        float2 u2 = __half22float2(*(const __half2*)&g_h1h[s2 * F1 + lane * 2]);
        float2 u3 = __half22float2(*(const __half2*)&g_h1h[s3 * F1 + lane * 2]);
        acc.x += u0.x + u1.x + u2.x + u3.x;
        acc.y += u0.y + u1.y + u2.y + u3.y;
    }
    for (; i < len; i++) {
        int s = idx[i];
        float2 u = __half22float2(*(const __half2*)&g_h1h[s * F1 + lane * 2]);
        acc.x += u.x; acc.y += u.y;
    }

    float dv = g_dinv[v];
    float t0 = dv * acc.x + b1[lane * 2];
    float t1 = dv * acc.y + b1[lane * 2 + 1];
    t0 = t0 >= 0.f ? t0 : 0.2f * t0;
    t1 = t1 >= 0.f ? t1 : 0.2f * t1;
    *(float2*)&g_t[v * F1 + lane * 2] = make_float2(t0, t1);
}

// ---------------------------------------------------------------------------
// GEMM2: h2[v,:] = (t[v,:] @ W2) * dinv[v]    [N,64]x[64,16]
// ---------------------------------------------------------------------------
__global__ void gcn_gemm2_kernel(const float* __restrict__ W2) {
    __shared__ __align__(16) float W2s[F1 * F2];
    __shared__ __align__(16) float ts[16][F1];
    int tid = threadIdx.x;
    for (int i = tid; i < F1 * F2; i += 256) W2s[i] = W2[i];

    int v0 = blockIdx.x * 16;
    for (int i = tid; i < 16 * 16; i += 256) {
        int r = i >> 4, q = i & 15;
        *(float4*)&ts[r][q * 4] = *(const float4*)&g_t[(v0 + r) * F1 + q * 4];
    }
    __syncthreads();

    int r = tid >> 4;
    int m = tid & 15;
    int v = v0 + r;
    float acc = 0.f;
#pragma unroll
    for (int j = 0; j < F1; j++) acc += ts[r][j] * W2s[j * F2 + m];
    g_h2[v * F2 + m] = acc * g_dinv[v];
}

// ---------------------------------------------------------------------------
// Layer-2 aggregation + log_softmax (warp per node)
// ---------------------------------------------------------------------------
__global__ void gcn_agg2_kernel(const float* __restrict__ b2,
                                float* __restrict__ out) {
    int w = (blockIdx.x * blockDim.x + threadIdx.x) >> 5;
    int lane = threadIdx.x & 31;
    if (w >= NNODES) return;
    int v = w;
    int beg = g_rowptr[v];
    int len = g_hist[v];
    int f = lane & 15;

    float acc = 0.f;
    const int* __restrict__ idx = &g_csr[beg];
    for (int i = (lane >> 4); i < len; i += 2) {
        int s = idx[i];
        acc += g_h2[s * F2 + f];
    }
    acc += __shfl_down_sync(0xffffffffu, acc, 16);

    float dv = g_dinv[v];
    float t = dv * (acc + g_h2[v * F2 + f]) + b2[f];

    float mx = t;
#pragma unroll
    for (int o = 8; o >= 1; o >>= 1)
        mx = fmaxf(mx, __shfl_xor_sync(0xffffffffu, mx, o));
    float ex = expf(t - mx);
    float sum = ex;
#pragma unroll
    for (int o = 8; o >= 1; o >>= 1)
        sum += __shfl_xor_sync(0xffffffffu, sum, o);
    float lse = mx + logf(sum);

    if (lane < 16) out[v * F2 + f] = t - lse;
}

// ---------------------------------------------------------------------------
// Launch: fork-join graph.
//   stream A: transpose -> (after hist) gemm1
//   stream 0: init -> hist -> scan1 -> scan2 -> rowptr -> permute
//   join:     agg1 -> gemm2 -> agg2 on stream 0
// Streams/events created per call (host-side only; graph replay is what is
// timed). No device memory is allocated.
// ---------------------------------------------------------------------------
extern "C" void kernel_launch(void* const* d_in, const int* in_sizes, int n_in,
                              void* d_out, int out_size) {
    const float* x  = (const float*)d_in[0];
    const int*   ei = (const int*)  d_in[1];
    const float* W1 = (const float*)d_in[2];
    const float* b1 = (const float*)d_in[3];
    const float* W2 = (const float*)d_in[4];
    const float* b2 = (const float*)d_in[5];
    float* out = (float*)d_out;

    const int* src = ei;
    const int* dst = ei + NEDGES;

    const int gemm1_smem = KC * F1 * 8 + KC * PX * 4;   // 32KB + 33.8KB = 65.8KB
    cudaFuncSetAttribute(gcn_gemm1_kernel,
                         cudaFuncAttributeMaxDynamicSharedMemorySize, gemm1_smem);

    cudaStream_t sA;
    cudaStreamCreateWithFlags(&sA, cudaStreamNonBlocking);
    cudaEvent_t ev0, evH, evG;
    cudaEventCreateWithFlags(&ev0, cudaEventDisableTiming);
    cudaEventCreateWithFlags(&evH, cudaEventDisableTiming);
    cudaEventCreateWithFlags(&evG, cudaEventDisableTiming);

    // fork: side stream joins the capture by waiting on an origin-stream event
    cudaEventRecord(ev0, 0);
    cudaStreamWaitEvent(sA, ev0, 0);

    dim3 tgrid(NP / 32, F0 / 32);
    gcn_transpose_kernel<<<tgrid, dim3(32, 8), 0, sA>>>(x);   // branch A

    gcn_init_kernel<<<(NNODES + 255) / 256, 256>>>();         // stream 0
    gcn_hist_kernel<<<(NEDGES + 255) / 256, 256>>>(dst);
    cudaEventRecord(evH, 0);
    cudaStreamWaitEvent(sA, evH, 0);                          // gemm1 needs hist

    gcn_gemm1_kernel<<<(NNODES + BM - 1) / BM, 256, gemm1_smem, sA>>>(W1);
    cudaEventRecord(evG, sA);

    gcn_scan1_kernel <<<NB1, 256>>>();                        // stream 0, overlaps gemm1
    gcn_scan2_kernel <<<1, 512>>>();
    gcn_rowptr_kernel<<<(NNODES + 255) / 256, 256>>>();
    gcn_permute_kernel<<<(NEDGES + 255) / 256, 256>>>(src, dst);

    cudaStreamWaitEvent(0, evG, 0);                           // join
    gcn_agg1_kernel <<<(NNODES * 32 + 255) / 256, 256>>>(b1);
    gcn_gemm2_kernel<<<NNODES / 16, 256>>>(W2);
    gcn_agg2_kernel <<<(NNODES * 32 + 255) / 256, 256>>>(b2, out);
    // streams/events intentionally not destroyed mid-capture; kernel_launch
    // is called only a handful of times (correctness + capture).
}

// round 10
// speedup vs baseline: 1.4040x; 1.2137x over previous
#include <cuda_runtime.h>
#include <cuda_fp16.h>
#include <mma.h>

#define NNODES 100000
#define NP 100224               // padded node count (multiple of 128)
#define NEDGES 1600000
#define F0 128
#define F1 64
#define F2 16
#define NB1 ((NNODES + 255) / 256)   // 391 scan blocks

// Scratch (device globals: allocation-free, graph-safe)
__device__ float  g_dinv[NNODES];
__device__ __half g_h1h [NNODES * F1];   // h~ = (x@W1)*dinv[row], fp16 for gathers
__device__ float  g_t   [NP * F1];       // gemm1 raw fp32 out, later agg1 output
__device__ float  g_h2  [NNODES * F2];   // h~2 = (t@W2)*dinv[row]
// dst-CSR scratch
__device__ int    g_hist  [NNODES];      // in-degree (dst)
__device__ int    g_off   [NNODES];
__device__ int    g_rowptr[NNODES];
__device__ int    g_cursor[NNODES];
__device__ int    g_bsum  [512];
__device__ int    g_csr   [NEDGES];      // src ids grouped by dst

// ---------------------------------------------------------------------------
// Init: zero dst histogram
// ---------------------------------------------------------------------------
__global__ void gcn_init_kernel() {
    int i = blockIdx.x * blockDim.x + threadIdx.x;
    if (i < NNODES) g_hist[i] = 0;
}

// ---------------------------------------------------------------------------
// In-degree histogram over dst (deg = 1 + hist)
// ---------------------------------------------------------------------------
__global__ void gcn_hist_kernel(const int* __restrict__ dst) {
    int e = blockIdx.x * blockDim.x + threadIdx.x;
    if (e < NEDGES) atomicAdd(&g_hist[dst[e]], 1);
}

// ---------------------------------------------------------------------------
// dinv = rsqrt(1 + indeg)
// ---------------------------------------------------------------------------
__global__ void gcn_dinv_kernel() {
    int i = blockIdx.x * blockDim.x + threadIdx.x;
    if (i < NNODES) g_dinv[i] = rsqrtf(1.0f + (float)g_hist[i]);
}

// ---------------------------------------------------------------------------
// GEMM1 via wmma (HMMA mma.sync — baseline PTX, works on compute_103):
//    g_t[v,:] = x[v,:] @ W1        (fp16 inputs, fp32 accumulate)
// Per block: 128 rows x 64 cols x K=128. 256 threads = 8 warps;
// warp w owns C row-tile w (16 rows), loops 4 col-tiles x 8 k-steps.
// ---------------------------------------------------------------------------
#define A_LD 136               // halfs per A row (pad vs bank conflicts)
#define B_LD 72                // halfs per B row
extern __shared__ __half s_wm[];

__global__ void gcn_gemm1_wmma(const float* __restrict__ x,
                               const float* __restrict__ W1) {
    using namespace nvcuda::wmma;
    __half* As = s_wm;                      // 128 * 136 halfs = 34816 B
    __half* Bs = s_wm + 128 * A_LD;         // 128 * 72 halfs  = 18432 B
    int tid = threadIdx.x, wid = tid >> 5;
    int row0 = blockIdx.x * 128;

    // Stage A: x rows -> fp16 (coalesced float4 loads, 8B STS)
    for (int i = tid; i < 128 * 32; i += 256) {
        int r = i >> 5, q = i & 31;
        int v = row0 + r;
        float4 xv = (v < NNODES) ? *(const float4*)&x[v * F0 + q * 4]
                                 : make_float4(0.f, 0.f, 0.f, 0.f);
        *(__half2*)&As[r * A_LD + q * 4]     = __floats2half2_rn(xv.x, xv.y);
        *(__half2*)&As[r * A_LD + q * 4 + 2] = __floats2half2_rn(xv.z, xv.w);
    }
    // Stage B: W1 [K=128][N=64] -> fp16
    for (int i = tid; i < 128 * 32; i += 256) {
        int k = i >> 5, n = (i & 31) * 2;
        float2 w = *(const float2*)&W1[k * F1 + n];
        *(__half2*)&Bs[k * B_LD + n] = __floats2half2_rn(w.x, w.y);
    }
    __syncthreads();

    fragment<accumulator, 16, 16, 16, float> acc[4];
#pragma unroll
    for (int c = 0; c < 4; c++) fill_fragment(acc[c], 0.0f);

    fragment<matrix_a, 16, 16, 16, __half, row_major> af;
    fragment<matrix_b, 16, 16, 16, __half, row_major> bf;
#pragma unroll
    for (int k = 0; k < 8; k++) {
        load_matrix_sync(af, As + wid * 16 * A_LD + k * 16, A_LD);
#pragma unroll
        for (int c = 0; c < 4; c++) {
            load_matrix_sync(bf, Bs + k * 16 * B_LD + c * 16, B_LD);
            mma_sync(acc[c], af, bf, acc[c]);
        }
    }

    // Store raw fp32 result (g_t padded to NP rows; scaled later)
#pragma unroll
    for (int c = 0; c < 4; c++)
        store_matrix_sync(&g_t[(row0 + wid * 16) * F1 + c * 16], acc[c],
                          F1, mem_row_major);
}

// ---------------------------------------------------------------------------
// scale_h1: g_h1h[v,:] = fp16( g_t[v,:] * dinv[v] )
// ---------------------------------------------------------------------------
__global__ void gcn_scale_h1_kernel() {
    int t = blockIdx.x * blockDim.x + threadIdx.x;
    if (t >= NNODES * 32) return;
    int v = t >> 5, j = (t & 31) * 2;
    float dv = g_dinv[v];
    float2 u = *(const float2*)&g_t[v * F1 + j];
    *(__half2*)&g_h1h[v * F1 + j] = __floats2half2_rn(u.x * dv, u.y * dv);
}

// ---------------------------------------------------------------------------
// Two-level exclusive scan of g_hist -> rowptr + cursor
// ---------------------------------------------------------------------------
__global__ void gcn_scan1_kernel() {
    __shared__ int s[256];
    int tid = threadIdx.x;
    int i = blockIdx.x * 256 + tid;
    int v = (i < NNODES) ? g_hist[i] : 0;
    s[tid] = v;
    __syncthreads();
#pragma unroll
    for (int o = 1; o < 256; o <<= 1) {
        int t = (tid >= o) ? s[tid - o] : 0;
        __syncthreads();
        s[tid] += t;
        __syncthreads();
    }
    if (i < NNODES) g_off[i] = s[tid] - v;
    if (tid == 255) g_bsum[blockIdx.x] = s[255];
}

__global__ void gcn_scan2_kernel() {
    __shared__ int s[512];
    int tid = threadIdx.x;
    int v = (tid < NB1) ? g_bsum[tid] : 0;
    s[tid] = v;
    __syncthreads();
#pragma unroll
    for (int o = 1; o < 512; o <<= 1) {
        int t = (tid >= o) ? s[tid - o] : 0;
        __syncthreads();
        s[tid] += t;
        __syncthreads();
    }
    if (tid < NB1) g_bsum[tid] = s[tid] - v;
}

__global__ void gcn_rowptr_kernel() {
    int i = blockIdx.x * blockDim.x + threadIdx.x;
    if (i < NNODES) {
        int p = g_off[i] + g_bsum[i >> 8];
        g_rowptr[i] = p;
        g_cursor[i] = p;
    }
}

// ---------------------------------------------------------------------------
// Permute: group src ids by dst (CSR fill)
// ---------------------------------------------------------------------------
__global__ void gcn_permute_kernel(const int* __restrict__ src,
                                   const int* __restrict__ dst) {
    int e = blockIdx.x * blockDim.x + threadIdx.x;
    if (e < NEDGES) {
        int d = dst[e];
        int p = atomicAdd(&g_cursor[d], 1);
        g_csr[p] = src[e];
    }
}

// ---------------------------------------------------------------------------
// Layer-1 aggregation + activation (warp per node, half2 per lane):
//    t[v] = leaky_relu(dinv[v] * (h1[v] + sum_{s->v} h1[s]) + b1)
// (writes g_t — safe: scale_h1 consumed g_t before this runs)
// ---------------------------------------------------------------------------
__global__ void gcn_agg1_kernel(const float* __restrict__ b1) {
    int w = (blockIdx.x * blockDim.x + threadIdx.x) >> 5;
    int lane = threadIdx.x & 31;
    if (w >= NNODES) return;
    int v = w;
    int beg = g_rowptr[v];
    int len = g_hist[v];

    float2 acc = __half22float2(*(const __half2*)&g_h1h[v * F1 + lane * 2]);

    const int* __restrict__ idx = &g_csr[beg];
    int i = 0;
    for (; i + 4 <= len; i += 4) {
        int s0 = idx[i], s1 = idx[i + 1], s2 = idx[i + 2], s3 = idx[i + 3];
        float2 u0 = __half22float2(*(const __half2*)&g_h1h[s0 * F1 + lane * 2]);
        float2 u1 = __half22float2(*(const __half2*)&g_h1h[s1 * F1 + lane * 2]);
        float2 u2 = __half22float2(*(const __half2*)&g_h1h[s2 * F1 + lane * 2]);
        float2 u3 = __half22float2(*(const __half2*)&g_h1h[s3 * F1 + lane * 2]);
        acc.x += u0.x + u1.x + u2.x + u3.x;
        acc.y += u0.y + u1.y + u2.y + u3.y;
    }
    for (; i < len; i++) {
        int s = idx[i];
        float2 u = __half22float2(*(const __half2*)&g_h1h[s * F1 + lane * 2]);
        acc.x += u.x; acc.y += u.y;
    }

    float dv = g_dinv[v];
    float t0 = dv * acc.x + b1[lane * 2];
    float t1 = dv * acc.y + b1[lane * 2 + 1];
    t0 = t0 >= 0.f ? t0 : 0.2f * t0;
    t1 = t1 >= 0.f ? t1 : 0.2f * t1;
    *(float2*)&g_t[v * F1 + lane * 2] = make_float2(t0, t1);
}

// ---------------------------------------------------------------------------
// GEMM2: h2[v,:] = (t[v,:] @ W2) * dinv[v]    [N,64]x[64,16]
// ---------------------------------------------------------------------------
__global__ void gcn_gemm2_kernel(const float* __restrict__ W2) {
    __shared__ __align__(16) float W2s[F1 * F2];
    __shared__ __align__(16) float ts[16][F1];
    int tid = threadIdx.x;
    for (int i = tid; i < F1 * F2; i += 256) W2s[i] = W2[i];

    int v0 = blockIdx.x * 16;
    for (int i = tid; i < 16 * 16; i += 256) {
        int r = i >> 4, q = i & 15;
        *(float4*)&ts[r][q * 4] = *(const float4*)&g_t[(v0 + r) * F1 + q * 4];
    }
    __syncthreads();

    int r = tid >> 4;
    int m = tid & 15;
    int v = v0 + r;
    float acc = 0.f;
#pragma unroll
    for (int j = 0; j < F1; j++) acc += ts[r][j] * W2s[j * F2 + m];
    g_h2[v * F2 + m] = acc * g_dinv[v];
}

// ---------------------------------------------------------------------------
// Layer-2 aggregation + log_softmax (warp per node)
// ---------------------------------------------------------------------------
__global__ void gcn_agg2_kernel(const float* __restrict__ b2,
                                float* __restrict__ out) {
    int w = (blockIdx.x * blockDim.x + threadIdx.x) >> 5;
    int lane = threadIdx.x & 31;
    if (w >= NNODES) return;
    int v = w;
    int beg = g_rowptr[v];
    int len = g_hist[v];
    int f = lane & 15;

    float acc = 0.f;
    const int* __restrict__ idx = &g_csr[beg];
    for (int i = (lane >> 4); i < len; i += 2) {
        int s = idx[i];
        acc += g_h2[s * F2 + f];
    }
    acc += __shfl_down_sync(0xffffffffu, acc, 16);

    float dv = g_dinv[v];
    float t = dv * (acc + g_h2[v * F2 + f]) + b2[f];

    float mx = t;
#pragma unroll
    for (int o = 8; o >= 1; o >>= 1)
        mx = fmaxf(mx, __shfl_xor_sync(0xffffffffu, mx, o));
    float ex = expf(t - mx);
    float sum = ex;
#pragma unroll
    for (int o = 8; o >= 1; o >>= 1)
        sum += __shfl_xor_sync(0xffffffffu, sum, o);
    float lse = mx + logf(sum);

    if (lane < 16) out[v * F2 + f] = t - lse;
}

// ---------------------------------------------------------------------------
// Launch: fork-join graph.
//   stream A: gemm1_wmma (no deps) -> (after dinv) scale_h1
//   stream 0: init -> hist -> dinv -> scan1 -> scan2 -> rowptr -> permute
//   join:     agg1 (needs scale_h1 + permute) -> gemm2 -> agg2
// ---------------------------------------------------------------------------
extern "C" void kernel_launch(void* const* d_in, const int* in_sizes, int n_in,
                              void* d_out, int out_size) {
    const float* x  = (const float*)d_in[0];
    const int*   ei = (const int*)  d_in[1];
    const float* W1 = (const float*)d_in[2];
    const float* b1 = (const float*)d_in[3];
    const float* W2 = (const float*)d_in[4];
    const float* b2 = (const float*)d_in[5];
    float* out = (float*)d_out;

    const int* src = ei;
    const int* dst = ei + NEDGES;

    const int g1_smem = (128 * A_LD + 128 * B_LD) * (int)sizeof(__half); // 53.2KB
    cudaFuncSetAttribute(gcn_gemm1_wmma,
                         cudaFuncAttributeMaxDynamicSharedMemorySize, g1_smem);

    cudaStream_t sA;
    cudaStreamCreateWithFlags(&sA, cudaStreamNonBlocking);
    cudaEvent_t ev0, evD, evS;
    cudaEventCreateWithFlags(&ev0, cudaEventDisableTiming);
    cudaEventCreateWithFlags(&evD, cudaEventDisableTiming);
    cudaEventCreateWithFlags(&evS, cudaEventDisableTiming);

    // fork: side stream joins the capture
    cudaEventRecord(ev0, 0);
    cudaStreamWaitEvent(sA, ev0, 0);

    gcn_gemm1_wmma<<<NP / 128, 256, g1_smem, sA>>>(x, W1);   // branch A

    gcn_init_kernel<<<(NNODES + 255) / 256, 256>>>();        // stream 0
    gcn_hist_kernel<<<(NEDGES + 255) / 256, 256>>>(dst);
    gcn_dinv_kernel<<<(NNODES + 255) / 256, 256>>>();
    cudaEventRecord(evD, 0);

    cudaStreamWaitEvent(sA, evD, 0);                         // scale needs dinv
    gcn_scale_h1_kernel<<<(NNODES * 32 + 255) / 256, 256, 0, sA>>>();
    cudaEventRecord(evS, sA);

    gcn_scan1_kernel <<<NB1, 256>>>();                       // stream 0
    gcn_scan2_kernel <<<1, 512>>>();
    gcn_rowptr_kernel<<<(NNODES + 255) / 256, 256>>>();
    gcn_permute_kernel<<<(NEDGES + 255) / 256, 256>>>(src, dst);

    cudaStreamWaitEvent(0, evS, 0);                          // join
    gcn_agg1_kernel <<<(NNODES * 32 + 255) / 256, 256>>>(b1);
    gcn_gemm2_kernel<<<NNODES / 16, 256>>>(W2);
    gcn_agg2_kernel <<<(NNODES * 32 + 255) / 256, 256>>>(b2, out);
}